// round 1
// baseline (speedup 1.0000x reference)
#include <cuda_runtime.h>
#include <cstdint>

#define C_CLUST 64
#define D_DIM   16
#define NCOPY   16

// Scratch (no allocations allowed -> __device__ globals)
__device__ float4 g_sums[NCOPY][C_CLUST][4];   // [copy][cluster][dim-group of 4]
__device__ float  g_cnts[NCOPY][C_CLUST];
__device__ float  g_cnt[C_CLUST];
__device__ float  g_invCD[C_CLUST];            // 1 / (C * max(count,1))
__device__ float  g_means[C_CLUST * D_DIM];    // [c][d]
__device__ float  g_meansT[D_DIM * C_CLUST];   // [d][c]
__device__ float  g_var;

__device__ __forceinline__ void red_add_f32(float* addr, float v) {
    asm volatile("red.global.add.f32 [%0], %1;" :: "l"(addr), "f"(v) : "memory");
}
__device__ __forceinline__ void red_add_v4(float4* addr, float4 v) {
    asm volatile("red.global.add.v4.f32 [%0], {%1, %2, %3, %4};"
                 :: "l"(addr), "f"(v.x), "f"(v.y), "f"(v.z), "f"(v.w) : "memory");
}

// ---------------------------------------------------------------- zero scratch
__global__ void k_zero() {
    int tid = blockIdx.x * blockDim.x + threadIdx.x;
    int stride = gridDim.x * blockDim.x;
    float4 z4 = make_float4(0.f, 0.f, 0.f, 0.f);
    for (int i = tid; i < NCOPY * C_CLUST * 4; i += stride)
        ((float4*)g_sums)[i] = z4;
    for (int i = tid; i < NCOPY * C_CLUST; i += stride)
        ((float*)g_cnts)[i] = 0.f;
    if (tid == 0) g_var = 0.f;
}

// ---------------------------------------------------------------- pass 1: sums + counts
// One lane per float4 (4 lanes cover one point). Coalesced loads.
// Feature adds: red.global.add.v4.f32 into one of NCOPY scratch copies.
// Counts: warp-aggregated via __match_any_sync (popc/4 per leader).
__global__ void __launch_bounds__(256) k_pass1(const float4* __restrict__ feat4,
                                               const int* __restrict__ labels,
                                               int n4) {
    const int copy = blockIdx.x & (NCOPY - 1);
    const int lane = threadIdx.x & 31;
    const int stride = gridDim.x * blockDim.x;
    for (int j = blockIdx.x * blockDim.x + threadIdx.x; j - lane < n4; j += stride) {
        bool active = (j < n4);
        unsigned am = __ballot_sync(0xffffffffu, active);
        if (active) {
            int point = j >> 2;
            int g     = j & 3;
            int lab   = labels[point];
            float4 v  = feat4[j];
            red_add_v4(&g_sums[copy][lab][g], v);
            // count: each point appears as a 4-lane group with identical label
            unsigned mm = __match_any_sync(am, lab);
            int leader = __ffs(mm) - 1;
            if (lane == leader)
                red_add_f32(&g_cnts[copy][lab], (float)__popc(mm) * 0.25f);
        }
    }
}

// ---------------------------------------------------------------- means (1 block, 1024 thr)
__global__ void k_means() {
    int t = threadIdx.x;
    if (t < C_CLUST) {
        float c = 0.f;
        #pragma unroll
        for (int k = 0; k < NCOPY; k++) c += g_cnts[k][t];
        g_cnt[t] = c;
        g_invCD[t] = 1.f / ((float)C_CLUST * fmaxf(c, 1.f));
    }
    __syncthreads();
    int c = t >> 4, d = t & 15;
    const float* base = (const float*)g_sums;
    float s = 0.f;
    #pragma unroll
    for (int k = 0; k < NCOPY; k++) s += base[(k * C_CLUST + c) * 16 + d];
    float m = s / fmaxf(g_cnt[c], 1.f);
    g_means[c * 16 + d]  = m;
    g_meansT[d * 64 + c] = m;
}

// ---------------------------------------------------------------- pass 2: variance hinge
// var_loss = sum over points of hinge(||x - mu + eps|| - 0.5)^2 * invCD[label]
// -> single global scalar, no per-cluster atomics.
__global__ void __launch_bounds__(256) k_pass2(const float4* __restrict__ feat4,
                                               const int* __restrict__ labels,
                                               int n4) {
    __shared__ float s_mT[D_DIM][C_CLUST + 1];   // pad to 65 words -> low conflicts
    __shared__ float s_inv[C_CLUST];
    __shared__ float s_w[8];

    for (int i = threadIdx.x; i < C_CLUST * D_DIM; i += blockDim.x)
        s_mT[i >> 6][i & 63] = g_meansT[i];
    if (threadIdx.x < C_CLUST) s_inv[threadIdx.x] = g_invCD[threadIdx.x];
    __syncthreads();

    const int lane = threadIdx.x & 31;
    const int stride = gridDim.x * blockDim.x;
    float local = 0.f;

    for (int j = blockIdx.x * blockDim.x + threadIdx.x; j - lane < n4; j += stride) {
        bool active = (j < n4);
        float p = 0.f;
        int lab = 0, g = 0;
        if (active) {
            int point = j >> 2;
            g   = j & 3;
            lab = labels[point];
            float4 v = feat4[j];
            int d0 = g * 4;
            float dx = v.x - s_mT[d0 + 0][lab] + 1e-8f;
            float dy = v.y - s_mT[d0 + 1][lab] + 1e-8f;
            float dz = v.z - s_mT[d0 + 2][lab] + 1e-8f;
            float dw = v.w - s_mT[d0 + 3][lab] + 1e-8f;
            p = dx * dx + dy * dy + dz * dz + dw * dw;
        }
        // combine the 4 dim-group partials of each point (lanes 4k..4k+3)
        p += __shfl_xor_sync(0xffffffffu, p, 1);
        p += __shfl_xor_sync(0xffffffffu, p, 2);
        if (active && g == 0) {
            float dist = sqrtf(p);
            float h = fmaxf(dist - 0.5f, 0.f);
            local += h * h * s_inv[lab];
        }
    }

    // block reduce -> one global red per block
    #pragma unroll
    for (int o = 16; o > 0; o >>= 1)
        local += __shfl_xor_sync(0xffffffffu, local, o);
    if (lane == 0) s_w[threadIdx.x >> 5] = local;
    __syncthreads();
    if (threadIdx.x == 0) {
        float s = 0.f;
        #pragma unroll
        for (int w = 0; w < 8; w++) s += s_w[w];
        red_add_f32(&g_var, s);
    }
}

// ---------------------------------------------------------------- finalize (1 block, 256 thr)
__global__ void k_final(float* __restrict__ out) {
    __shared__ float s_m[C_CLUST][D_DIM];
    __shared__ float s_red[256];
    int t = threadIdx.x;
    for (int i = t; i < C_CLUST * D_DIM; i += 256)
        ((float*)s_m)[i] = g_means[i];
    __syncthreads();

    // reg: per-cluster norms of (mean + eps)
    float regp = 0.f;
    if (t < C_CLUST) {
        float s = 0.f;
        #pragma unroll
        for (int d = 0; d < D_DIM; d++) {
            float v = s_m[t][d] + 1e-8f;
            s += v * v;
        }
        regp = sqrtf(s);
    }

    // dist: all ordered pairs i != j
    float dl = 0.f;
    for (int p = t; p < C_CLUST * C_CLUST; p += 256) {
        int i = p >> 6, jj = p & 63;
        if (i != jj) {
            float s = 0.f;
            #pragma unroll
            for (int d = 0; d < D_DIM; d++) {
                float df = s_m[i][d] - s_m[jj][d] + 1e-8f;
                s += df * df;
            }
            float pd = sqrtf(s);
            float h = fmaxf(3.0f - pd, 0.f);   // 2 * DELTA_DIST = 3.0
            dl += h * h;
        }
    }

    s_red[t] = dl; __syncthreads();
    for (int o = 128; o > 0; o >>= 1) { if (t < o) s_red[t] += s_red[t + o]; __syncthreads(); }
    float dist_loss = s_red[0] / (float)(C_CLUST * (C_CLUST - 1));
    __syncthreads();

    s_red[t] = regp; __syncthreads();
    for (int o = 128; o > 0; o >>= 1) { if (t < o) s_red[t] += s_red[t + o]; __syncthreads(); }
    float reg_loss = s_red[0] / (float)C_CLUST;

    if (t == 0) {
        float var_loss = g_var;
        out[0] = var_loss + dist_loss + 0.001f * reg_loss;
        out[1] = var_loss;
        out[2] = dist_loss;
        out[3] = reg_loss;
    }
}

// ---------------------------------------------------------------- launch
extern "C" void kernel_launch(void* const* d_in, const int* in_sizes, int n_in,
                              void* d_out, int out_size) {
    const float4* feat4  = (const float4*)d_in[0];
    const int*    labels = (const int*)d_in[1];
    int N  = in_sizes[1];     // number of points (labels count)
    int n4 = N * 4;           // float4 count of features (D=16 -> 4 float4/point)

    k_zero <<<68, 256>>>();
    k_pass1<<<148 * 8, 256>>>(feat4, labels, n4);
    k_means<<<1, 1024>>>();
    k_pass2<<<148 * 8, 256>>>(feat4, labels, n4);
    k_final<<<1, 256>>>((float*)d_out);
}

// round 2
// speedup vs baseline: 1.8832x; 1.8832x over previous
#include <cuda_runtime.h>
#include <cstdint>

#define C_CLUST   64
#define NCOPY     16
#define ACC_STRIDE 17                      // 16 dims + 1 count slot
#define ACC_SIZE  (C_CLUST * ACC_STRIDE)   // 1088

// Scratch (no allocations allowed -> __device__ globals)
__device__ float  g_acc[NCOPY][ACC_SIZE];
__device__ float  g_cnt[C_CLUST];
__device__ float  g_invCD[C_CLUST];           // 1 / (C * max(count,1))
__device__ float  g_means[C_CLUST * 16];      // [c][d]
__device__ float4 g_m4[4 * C_CLUST];          // [g*64 + c] = means[c][4g..4g+3]
__device__ float  g_var;

__device__ __forceinline__ void red_add_f32(float* addr, float v) {
    asm volatile("red.global.add.f32 [%0], %1;" :: "l"(addr), "f"(v) : "memory");
}

// ---------------------------------------------------------------- zero scratch
__global__ void k_zero() {
    int tid = blockIdx.x * blockDim.x + threadIdx.x;
    int stride = gridDim.x * blockDim.x;
    float* a = (float*)g_acc;
    for (int i = tid; i < NCOPY * ACC_SIZE; i += stride) a[i] = 0.f;
    if (tid == 0) g_var = 0.f;
}

// ---------------------------------------------------------------- pass 1
// Per-warp private shared accumulator (no atomics). Each warp-iteration
// loads 8 points (32 float4, coalesced) + 8 labels (one 32B sector).
// shfl-transpose to lane = half*16 + dim; each half accumulates one point.
// Cross-half same-label collision merged into the upper half.
__global__ void __launch_bounds__(256) k_pass1(const float4* __restrict__ feat4,
                                               const int* __restrict__ labels,
                                               int npts) {
    __shared__ float s_acc[8][ACC_SIZE];

    const int wid  = threadIdx.x >> 5;
    const int lane = threadIdx.x & 31;
    float* acc = s_acc[wid];
    for (int i = lane; i < ACC_SIZE; i += 32) acc[i] = 0.f;
    __syncwarp();

    const int d    = lane & 15;     // dim this lane accumulates
    const int half = lane >> 4;     // 0 = first point of pair, 1 = second
    const int comp = lane & 3;      // float4 component of d
    const int gw     = blockIdx.x * 8 + wid;
    const int nwarp  = gridDim.x * 8;

    for (int base = gw * 8; base < npts; base += nwarp * 8) {
        // load: 32 consecutive float4 = 8 points
        int pt = base + (lane >> 2);
        float4 f = make_float4(0.f, 0.f, 0.f, 0.f);
        if (pt < npts) f = __ldcs(&feat4[base * 4 + lane]);
        int lab = -1;
        if (lane < 8) {
            int p = base + lane;
            if (p < npts) lab = labels[p];
        }

        #pragma unroll
        for (int r = 0; r < 4; r++) {
            __syncwarp();                                 // order prior STS vs next LDS
            int   myp  = 2 * r + half;                    // point 0..7 for this half
            int   labm = __shfl_sync(0xffffffffu, lab, myp);
            int   src  = 4 * myp + (d >> 2);
            float c0 = __shfl_sync(0xffffffffu, f.x, src);
            float c1 = __shfl_sync(0xffffffffu, f.y, src);
            float c2 = __shfl_sync(0xffffffffu, f.z, src);
            float c3 = __shfl_sync(0xffffffffu, f.w, src);
            float v  = (comp & 1) ? ((comp & 2) ? c3 : c1)
                                  : ((comp & 2) ? c2 : c0);
            int   labo = __shfl_xor_sync(0xffffffffu, labm, 16);
            float vo   = __shfl_xor_sync(0xffffffffu, v, 16);
            bool mine  = (labm >= 0);
            bool dup   = mine && (labm == labo);          // both halves same cluster
            bool wr    = mine && !(dup && half == 0);     // lower half defers to upper
            float add  = v + ((dup && half == 1) ? vo : 0.f);
            if (wr) {
                int a = labm * ACC_STRIDE + d;
                acc[a] += add;
                if (d == 0)
                    acc[labm * ACC_STRIDE + 16] += (dup ? 2.f : 1.f);
            }
        }
    }

    // block reduce 8 warp copies -> 1 RED per element per block
    __syncthreads();
    const int copy = blockIdx.x & (NCOPY - 1);
    for (int idx = threadIdx.x; idx < ACC_SIZE; idx += 256) {
        float s = 0.f;
        #pragma unroll
        for (int w = 0; w < 8; w++) s += s_acc[w][idx];
        red_add_f32(&g_acc[copy][idx], s);
    }
}

// ---------------------------------------------------------------- means (1 block, 1024 thr)
__global__ void k_means() {
    __shared__ float s_cnt[C_CLUST];
    int t = threadIdx.x;
    if (t < C_CLUST) {
        float c = 0.f;
        #pragma unroll
        for (int k = 0; k < NCOPY; k++) c += g_acc[k][t * ACC_STRIDE + 16];
        g_cnt[t] = c;
        float sc = fmaxf(c, 1.f);
        s_cnt[t] = sc;
        g_invCD[t] = 1.f / ((float)C_CLUST * sc);
    }
    __syncthreads();
    int c = t >> 4, d = t & 15;
    float s = 0.f;
    #pragma unroll
    for (int k = 0; k < NCOPY; k++) s += g_acc[k][c * ACC_STRIDE + d];
    float m = s / s_cnt[c];
    g_means[c * 16 + d] = m;
    ((float*)g_m4)[((d >> 2) * C_CLUST + c) * 4 + (d & 3)] = m;
}

// ---------------------------------------------------------------- pass 2: variance hinge
// var_loss = sum_points hinge(||x - mu + eps|| - 0.5)^2 / (C * count[label])
__global__ void __launch_bounds__(256) k_pass2(const float4* __restrict__ feat4,
                                               const int* __restrict__ labels,
                                               int n4) {
    __shared__ float4 s_m4[4 * C_CLUST];
    __shared__ float  s_inv[C_CLUST];
    __shared__ float  s_w[8];

    if (threadIdx.x < 4 * C_CLUST) s_m4[threadIdx.x] = g_m4[threadIdx.x];
    if (threadIdx.x < C_CLUST)     s_inv[threadIdx.x] = g_invCD[threadIdx.x];
    __syncthreads();

    const int lane   = threadIdx.x & 31;
    const int g      = threadIdx.x & 3;   // invariant: strides are multiples of 4
    const int stride = gridDim.x * blockDim.x;
    float local = 0.f;

    for (int j = blockIdx.x * 256 + threadIdx.x; j - lane < n4; j += stride) {
        bool active = (j < n4);
        float p = 0.f;
        int lab = 0;
        if (active) {
            lab = labels[j >> 2];
            float4 v = __ldcs(&feat4[j]);
            float4 m = s_m4[g * C_CLUST + lab];
            float dx = v.x - m.x + 1e-8f;
            float dy = v.y - m.y + 1e-8f;
            float dz = v.z - m.z + 1e-8f;
            float dw = v.w - m.w + 1e-8f;
            p = fmaf(dx, dx, fmaf(dy, dy, fmaf(dz, dz, dw * dw)));
        }
        p += __shfl_xor_sync(0xffffffffu, p, 1);
        p += __shfl_xor_sync(0xffffffffu, p, 2);
        if (active && g == 0) {
            float dist = sqrtf(p);
            float h = fmaxf(dist - 0.5f, 0.f);
            local += h * h * s_inv[lab];
        }
    }

    #pragma unroll
    for (int o = 16; o > 0; o >>= 1)
        local += __shfl_xor_sync(0xffffffffu, local, o);
    if (lane == 0) s_w[threadIdx.x >> 5] = local;
    __syncthreads();
    if (threadIdx.x == 0) {
        float s = 0.f;
        #pragma unroll
        for (int w = 0; w < 8; w++) s += s_w[w];
        red_add_f32(&g_var, s);
    }
}

// ---------------------------------------------------------------- finalize (1 block, 256 thr)
__global__ void k_final(float* __restrict__ out) {
    __shared__ float s_m[C_CLUST][16];
    __shared__ float s_red[256];
    int t = threadIdx.x;
    for (int i = t; i < C_CLUST * 16; i += 256)
        ((float*)s_m)[i] = g_means[i];
    __syncthreads();

    float regp = 0.f;
    if (t < C_CLUST) {
        float s = 0.f;
        #pragma unroll
        for (int d = 0; d < 16; d++) {
            float v = s_m[t][d] + 1e-8f;
            s += v * v;
        }
        regp = sqrtf(s);
    }

    float dl = 0.f;
    for (int p = t; p < C_CLUST * C_CLUST; p += 256) {
        int i = p >> 6, jj = p & 63;
        if (i != jj) {
            float s = 0.f;
            #pragma unroll
            for (int d = 0; d < 16; d++) {
                float df = s_m[i][d] - s_m[jj][d] + 1e-8f;
                s += df * df;
            }
            float pd = sqrtf(s);
            float h = fmaxf(3.0f - pd, 0.f);   // 2 * DELTA_DIST
            dl += h * h;
        }
    }

    s_red[t] = dl; __syncthreads();
    for (int o = 128; o > 0; o >>= 1) { if (t < o) s_red[t] += s_red[t + o]; __syncthreads(); }
    float dist_loss = s_red[0] / (float)(C_CLUST * (C_CLUST - 1));
    __syncthreads();

    s_red[t] = regp; __syncthreads();
    for (int o = 128; o > 0; o >>= 1) { if (t < o) s_red[t] += s_red[t + o]; __syncthreads(); }
    float reg_loss = s_red[0] / (float)C_CLUST;

    if (t == 0) {
        float var_loss = g_var;
        out[0] = var_loss + dist_loss + 0.001f * reg_loss;
        out[1] = var_loss;
        out[2] = dist_loss;
        out[3] = reg_loss;
    }
}

// ---------------------------------------------------------------- launch
extern "C" void kernel_launch(void* const* d_in, const int* in_sizes, int n_in,
                              void* d_out, int out_size) {
    const float4* feat4  = (const float4*)d_in[0];
    const int*    labels = (const int*)d_in[1];
    int N  = in_sizes[1];     // number of points
    int n4 = N * 4;           // float4 count (D=16)

    k_zero <<<68, 256>>>();
    k_pass1<<<148 * 8, 256>>>(feat4, labels, N);
    k_means<<<1, 1024>>>();
    k_pass2<<<148 * 8, 256>>>(feat4, labels, n4);
    k_final<<<1, 256>>>((float*)d_out);
}